// round 11
// baseline (speedup 1.0000x reference)
#include <cuda_runtime.h>
#include <cuda_bf16.h>
#include <stdint.h>
#include <math.h>

#define BB 4
#define TT 2048
#define DD 128
#define HH 8
#define DK 16
#define KW 20          // smem K row stride (u32): 16 used (8 hi + 8 lo) + 4 pad
#define VW 68          // smem V^T d-row stride (u32): 64 used + 4 pad
#define NT (TT/128)    // 16 k-tiles

__device__ float    g_Q[BB*TT*DD];
__device__ uint32_t g_Kw[BB*HH*TT*16];     // [bh][row][16]: w<8 hi pairs, w>=8 lo
__device__ uint32_t g_Vt[BB*HH*DK*(TT/2)]; // [bh][d][p]: pack(V[2p][d],V[2p+1][d])
__device__ float    g_ctx[BB*TT*DD];

__device__ __forceinline__ void mma_bf16(float c[4], const uint32_t a[4],
                                         uint32_t b0, uint32_t b1) {
    asm volatile(
        "mma.sync.aligned.m16n8k16.row.col.f32.bf16.bf16.f32 "
        "{%0,%1,%2,%3}, {%4,%5,%6,%7}, {%8,%9}, {%0,%1,%2,%3};"
        : "+f"(c[0]), "+f"(c[1]), "+f"(c[2]), "+f"(c[3])
        : "r"(a[0]), "r"(a[1]), "r"(a[2]), "r"(a[3]), "r"(b0), "r"(b1));
}
__device__ __forceinline__ uint32_t pack_bf16x2(float lo, float hi) {
    __nv_bfloat162 v = __floats2bfloat162_rn(lo, hi);
    return *reinterpret_cast<uint32_t*>(&v);
}
__device__ __forceinline__ void split_pair(float a, float b,
                                           uint32_t& hi, uint32_t& lo) {
    __nv_bfloat162 h2 = __floats2bfloat162_rn(a, b);
    __nv_bfloat162 l2 = __floats2bfloat162_rn(a - __bfloat162float(h2.x),
                                              b - __bfloat162float(h2.y));
    hi = *reinterpret_cast<uint32_t*>(&h2);
    lo = *reinterpret_cast<uint32_t*>(&l2);
}
__device__ __forceinline__ float ex2(float x) {
    float y; asm("ex2.approx.f32 %0, %1;" : "=f"(y) : "f"(x)); return y;
}
__device__ __forceinline__ void cpa16(uint32_t dst, const void* src) {
    asm volatile("cp.async.ca.shared.global [%0], [%1], 16;" :: "r"(dst), "l"(src));
}
#define CPA_COMMIT() asm volatile("cp.async.commit_group;" ::: "memory")
#define CPA_WAIT(N)  asm volatile("cp.async.wait_group %0;" :: "n"(N) : "memory")

// ---------------------------------------------------------------------------
// Attention: grid (TT/64, BB*HH), 128 threads = 4 warps x one m16 fragment.
// Double-buffered cp.async fills; sweep1 = 1-term bf16 scores (normalizer),
// sweep2 = 3-term scores (outputs), streaming attn stores.
// ---------------------------------------------------------------------------
__global__ void __launch_bounds__(128, 6)
attn_mma_kernel(const float* __restrict__ Qg,
                const uint32_t* __restrict__ Kw,
                const uint32_t* __restrict__ Vt,
                float* __restrict__ attn,
                float* __restrict__ ctx)
{
    __shared__ __align__(16) uint32_t sK[2][128 * KW];
    __shared__ __align__(16) uint32_t sV[2][DK * VW];

    const int tid  = threadIdx.x;
    const int lane = tid & 31;
    const int wq   = tid >> 5;
    const int g    = lane >> 2;
    const int t    = lane & 3;

    const int q0 = blockIdx.x * 64;
    const int bh = blockIdx.y;
    const int bb = bh >> 3;
    const int h  = bh & 7;
    const int r0 = q0 + wq * 16 + g;

    const uint32_t sKa = (uint32_t)__cvta_generic_to_shared(sK);
    const uint32_t sVa = (uint32_t)__cvta_generic_to_shared(sV);
    const uint32_t* gkb = Kw + ((size_t)bh * TT + tid) * 16;

    // Q fragment: bf16 hi/lo, prescaled by 0.25*log2(e)
    uint32_t ahi[4], alo[4];
    {
        const float sc = 0.360673760f;
        const float* Qb = Qg + ((size_t)bb * TT + r0) * DD + h * DK;
        float2 x0 = *(const float2*)(Qb + 2 * t);
        float2 x1 = *(const float2*)(Qb + 8 * DD + 2 * t);
        float2 x2 = *(const float2*)(Qb + 2 * t + 8);
        float2 x3 = *(const float2*)(Qb + 8 * DD + 2 * t + 8);
        split_pair(sc * x0.x, sc * x0.y, ahi[0], alo[0]);
        split_pair(sc * x1.x, sc * x1.y, ahi[1], alo[1]);
        split_pair(sc * x2.x, sc * x2.y, ahi[2], alo[2]);
        split_pair(sc * x3.x, sc * x3.y, ahi[3], alo[3]);
    }

    // ---------------- sweep 1: rowsums (hi*hi only), double-buffered ----------------
    float ps0 = 0.f, ps1 = 0.f;
    {   // prologue: fill tile 0 into buf 0 (hi words only)
        const uint32_t d0 = sKa + tid * (KW * 4);
        cpa16(d0, gkb); cpa16(d0 + 16, gkb + 4);
        CPA_COMMIT();
    }
    for (int kt = 0; kt < NT; kt++) {
        if (kt + 1 < NT) {
            const uint32_t* gk = gkb + (size_t)(kt + 1) * 128 * 16;
            const uint32_t d  = sKa + (((kt + 1) & 1) * 128 * KW + tid * KW) * 4;
            cpa16(d, gk); cpa16(d + 16, gk + 4);
            CPA_COMMIT();
            CPA_WAIT(1);
        } else {
            CPA_WAIT(0);
        }
        __syncthreads();
        const uint32_t* sKb = sK[kt & 1];
        #pragma unroll 4
        for (int ns = 0; ns < 16; ns++) {
            const int base = (ns * 8 + g) * KW + t;
            float C[4] = {0.f, 0.f, 0.f, 0.f};
            mma_bf16(C, ahi, sKb[base], sKb[base + 4]);
            ps0 += ex2(C[0]) + ex2(C[1]);
            ps1 += ex2(C[2]) + ex2(C[3]);
        }
        __syncthreads();
    }
    ps0 += __shfl_xor_sync(0xffffffffu, ps0, 1);
    ps0 += __shfl_xor_sync(0xffffffffu, ps0, 2);
    ps1 += __shfl_xor_sync(0xffffffffu, ps1, 1);
    ps1 += __shfl_xor_sync(0xffffffffu, ps1, 2);
    const float lri0 = -__log2f(ps0);
    const float lri1 = -__log2f(ps1);

    // ---------------- sweep 2: 3-term scores, attn stores, PV ----------------
    float cc[2][4] = {{0.f,0.f,0.f,0.f},{0.f,0.f,0.f,0.f}};
    const size_t arow0 = ((size_t)bh * TT + r0) * TT;
    const size_t arow1 = arow0 + (size_t)8 * TT;
    const uint32_t* gvb = Vt + (size_t)bh * DK * (TT / 2);
    const int vd  = tid >> 3;            // 0..15 (d row), 8 threads per row
    const int vcw = (tid & 7) * 8;       // column word base (2 cpa16 of 4 words)

    {   // prologue: fill tile 0 (K hi+lo and V) into buf 0
        const uint32_t dk0 = sKa + tid * (KW * 4);
        #pragma unroll
        for (int c = 0; c < 4; c++) cpa16(dk0 + c * 16, gkb + c * 4);
        const uint32_t dv0 = sVa + (vd * VW + vcw) * 4;
        cpa16(dv0,      gvb + (size_t)vd * (TT / 2) + vcw);
        cpa16(dv0 + 16, gvb + (size_t)vd * (TT / 2) + vcw + 4);
        CPA_COMMIT();
    }
    for (int kt = 0; kt < NT; kt++) {
        if (kt + 1 < NT) {
            const int nb = (kt + 1) & 1;
            const uint32_t* gk = gkb + (size_t)(kt + 1) * 128 * 16;
            const uint32_t dk = sKa + (nb * 128 * KW + tid * KW) * 4;
            #pragma unroll
            for (int c = 0; c < 4; c++) cpa16(dk + c * 16, gk + c * 4);
            const uint32_t dv = sVa + ((nb * DK + vd) * VW + vcw) * 4;
            const uint32_t* gv = gvb + (size_t)vd * (TT / 2) + (kt + 1) * 64 + vcw;
            cpa16(dv, gv); cpa16(dv + 16, gv + 4);
            CPA_COMMIT();
            CPA_WAIT(1);
        } else {
            CPA_WAIT(0);
        }
        __syncthreads();
        const uint32_t* sKb = sK[kt & 1];
        const uint32_t* sVb = sV[kt & 1];

        #pragma unroll 2
        for (int j = 0; j < 8; j++) {
            uint32_t apk[4];
            #pragma unroll
            for (int nsl = 0; nsl < 2; nsl++) {
                const int base = ((j * 2 + nsl) * 8 + g) * KW + t;
                float C[4] = {lri0, lri0, lri1, lri1};
                mma_bf16(C, ahi, sKb[base],     sKb[base + 4]);
                mma_bf16(C, ahi, sKb[base + 8], sKb[base + 12]);
                mma_bf16(C, alo, sKb[base],     sKb[base + 4]);
                const float p0 = ex2(C[0]);
                const float p1 = ex2(C[1]);
                const float p2 = ex2(C[2]);
                const float p3 = ex2(C[3]);
                const int col = kt * 128 + j * 16 + nsl * 8 + 2 * t;
                __stcs((float2*)(attn + arow0 + col), make_float2(p0, p1));
                __stcs((float2*)(attn + arow1 + col), make_float2(p2, p3));
                apk[nsl ? 2 : 0] = pack_bf16x2(p0, p1);
                apk[nsl ? 3 : 1] = pack_bf16x2(p2, p3);
            }
            #pragma unroll
            for (int n2 = 0; n2 < 2; n2++) {
                const int vi = (n2 * 8 + g) * VW + 8 * j + t;
                mma_bf16(cc[n2], apk, sVb[vi], sVb[vi + 4]);
            }
        }
        __syncthreads();
    }

    #pragma unroll
    for (int n2 = 0; n2 < 2; n2++) {
        float* cp = ctx + ((size_t)bb * TT + r0) * DD + h * DK + n2 * 8 + 2 * t;
        *(float2*)cp            = make_float2(cc[n2][0], cc[n2][1]);
        *(float2*)(cp + 8 * DD) = make_float2(cc[n2][2], cc[n2][3]);
    }
}

// ---------------------------------------------------------------------------
// Merged QKV projection: grid (rows/16, 3), 128 threads.
// y==0 -> Q fp32; y==1 -> K packed bf16 hi/lo; y==2 -> V^T packed bf16x2
// ---------------------------------------------------------------------------
__global__ void proj3_kernel(const float* __restrict__ q,
                             const float* __restrict__ k,
                             const float* __restrict__ v,
                             const float* __restrict__ Wq, const float* __restrict__ bq,
                             const float* __restrict__ Wk, const float* __restrict__ bk,
                             const float* __restrict__ Wv, const float* __restrict__ bv,
                             float* __restrict__ Qd,
                             uint32_t* __restrict__ Kw,
                             uint32_t* __restrict__ Vt)
{
    const float* X; const float* W; const float* bias;
    if (blockIdx.y == 0)      { X = q; W = Wq; bias = bq; }
    else if (blockIdx.y == 1) { X = k; W = Wk; bias = bk; }
    else                      { X = v; W = Wv; bias = bv; }

    __shared__ float xs[16][132];
    const int tid  = threadIdx.x;
    const int row0 = blockIdx.x * 16;

    #pragma unroll
    for (int r = 0; r < 16; r++)
        xs[r][tid] = X[(size_t)(row0 + r) * DD + tid];
    __syncthreads();

    float acc[16];
    const float bvv = bias[tid];
    #pragma unroll
    for (int r = 0; r < 16; r++) acc[r] = bvv;

    #pragma unroll 4
    for (int kk = 0; kk < DD; kk += 4) {
        const float w0 = W[(kk + 0) * DD + tid];
        const float w1 = W[(kk + 1) * DD + tid];
        const float w2 = W[(kk + 2) * DD + tid];
        const float w3 = W[(kk + 3) * DD + tid];
        #pragma unroll
        for (int r = 0; r < 16; r++) {
            const float4 xv = *(const float4*)&xs[r][kk];
            acc[r] = fmaf(xv.x, w0, fmaf(xv.y, w1, fmaf(xv.z, w2, fmaf(xv.w, w3, acc[r]))));
        }
    }

    if (blockIdx.y == 0) {
        #pragma unroll
        for (int r = 0; r < 16; r++)
            Qd[(size_t)(row0 + r) * DD + tid] = acc[r];
        return;
    }

    __syncthreads();
    #pragma unroll
    for (int r = 0; r < 16; r++) xs[r][tid] = acc[r];
    __syncthreads();

    const int bbat = row0 >> 11;
    const int trow = row0 & 2047;

    if (blockIdx.y == 1) {
        #pragma unroll
        for (int i = 0; i < 16; i++) {
            const int widx = i * 128 + tid;
            const int r    = widx >> 7;
            const int rem  = widx & 127;
            const int hh2  = rem >> 4;
            const int w    = rem & 15;
            const int c    = hh2 * DK + (w & 7) * 2;
            const float a = xs[r][c], b = xs[r][c + 1];
            __nv_bfloat162 h2 = __floats2bfloat162_rn(a, b);
            uint32_t word;
            if (w < 8) word = *reinterpret_cast<uint32_t*>(&h2);
            else {
                __nv_bfloat162 l2 = __floats2bfloat162_rn(a - __bfloat162float(h2.x),
                                                          b - __bfloat162float(h2.y));
                word = *reinterpret_cast<uint32_t*>(&l2);
            }
            Kw[((size_t)(bbat * HH + hh2) * TT + trow + r) * 16 + w] = word;
        }
    } else {
        const int p0 = trow >> 1;
        #pragma unroll
        for (int i = 0; i < 8; i++) {
            const int widx = i * 128 + tid;
            const int hd  = widx >> 3;
            const int pl  = widx & 7;
            const int hh2 = hd >> 4, d = hd & 15;
            const int c   = hh2 * DK + d;
            const uint32_t word = pack_bf16x2(xs[2 * pl][c], xs[2 * pl + 1][c]);
            Vt[((size_t)(bbat * HH + hh2) * DK + d) * (TT / 2) + p0 + pl] = word;
        }
    }
}

// ---------------------------------------------------------------------------
// Output projection + residual + LayerNorm
// ---------------------------------------------------------------------------
__global__ void out_kernel(const float* __restrict__ ctxg,
                           const float* __restrict__ Wo,
                           const float* __restrict__ bo,
                           const float* __restrict__ resid,
                           const float* __restrict__ gamma,
                           const float* __restrict__ beta,
                           float* __restrict__ out)
{
    __shared__ float xs[16][132];
    __shared__ float mrow[16], rrow[16];
    const int tid  = threadIdx.x;
    const int row0 = blockIdx.x * 16;

    #pragma unroll
    for (int r = 0; r < 16; r++)
        xs[r][tid] = ctxg[(size_t)(row0 + r) * DD + tid];
    __syncthreads();

    float acc[16];
    const float bv = bo[tid];
    #pragma unroll
    for (int r = 0; r < 16; r++) acc[r] = bv;

    #pragma unroll 4
    for (int kk = 0; kk < DD; kk += 4) {
        const float w0 = Wo[(kk + 0) * DD + tid];
        const float w1 = Wo[(kk + 1) * DD + tid];
        const float w2 = Wo[(kk + 2) * DD + tid];
        const float w3 = Wo[(kk + 3) * DD + tid];
        #pragma unroll
        for (int r = 0; r < 16; r++) {
            const float4 xv = *(const float4*)&xs[r][kk];
            acc[r] = fmaf(xv.x, w0, fmaf(xv.y, w1, fmaf(xv.z, w2, fmaf(xv.w, w3, acc[r]))));
        }
    }
    __syncthreads();

    #pragma unroll
    for (int r = 0; r < 16; r++) {
        acc[r] += resid[(size_t)(row0 + r) * DD + tid];
        xs[r][tid] = acc[r];
    }
    __syncthreads();

    {
        const int r = tid >> 3, l8 = tid & 7;
        float s = 0.f, s2 = 0.f;
        for (int c = l8; c < 128; c += 8) {
            const float v = xs[r][c];
            s += v; s2 = fmaf(v, v, s2);
        }
        #pragma unroll
        for (int off = 4; off > 0; off >>= 1) {
            s  += __shfl_down_sync(0xffffffffu, s,  off, 8);
            s2 += __shfl_down_sync(0xffffffffu, s2, off, 8);
        }
        if (l8 == 0) {
            const float m   = s * (1.f / 128.f);
            const float var = s2 * (1.f / 128.f) - m * m;
            mrow[r] = m;
            rrow[r] = rsqrtf(var + 1e-5f);
        }
    }
    __syncthreads();

    const float gm = gamma[tid], bt = beta[tid];
    #pragma unroll
    for (int r = 0; r < 16; r++)
        out[(size_t)(row0 + r) * DD + tid] = (acc[r] - mrow[r]) * rrow[r] * gm + bt;
}

// ---------------------------------------------------------------------------
extern "C" void kernel_launch(void* const* d_in, const int* in_sizes, int n_in,
                              void* d_out, int out_size)
{
    const float* queries = (const float*)d_in[0];
    const float* keys    = (const float*)d_in[1];
    const float* values  = (const float*)d_in[2];
    const float* Wq      = (const float*)d_in[3];
    const float* bq      = (const float*)d_in[4];
    const float* Wk      = (const float*)d_in[5];
    const float* bk      = (const float*)d_in[6];
    const float* Wv      = (const float*)d_in[7];
    const float* bv      = (const float*)d_in[8];
    const float* Wo      = (const float*)d_in[9];
    const float* bo      = (const float*)d_in[10];
    const float* gamma   = (const float*)d_in[11];
    const float* beta    = (const float*)d_in[12];

    float* out  = (float*)d_out;
    float* attn = out + (size_t)BB * TT * DD;

    float *Qd, *Cd; uint32_t *Kwp, *Vtp;
    cudaGetSymbolAddress((void**)&Qd,  g_Q);
    cudaGetSymbolAddress((void**)&Kwp, g_Kw);
    cudaGetSymbolAddress((void**)&Vtp, g_Vt);
    cudaGetSymbolAddress((void**)&Cd,  g_ctx);

    const int rows = BB * TT;
    proj3_kernel<<<dim3(rows / 16, 3), 128>>>(queries, keys, values,
                                              Wq, bq, Wk, bk, Wv, bv,
                                              Qd, Kwp, Vtp);

    attn_mma_kernel<<<dim3(TT / 64, BB * HH), 128>>>(Qd, Kwp, Vtp, attn, Cd);

    out_kernel<<<rows / 16, 128>>>(Cd, Wo, bo, queries, gamma, beta, out);
}

// round 13
// speedup vs baseline: 1.0262x; 1.0262x over previous
#include <cuda_runtime.h>
#include <cuda_bf16.h>
#include <stdint.h>
#include <math.h>

#define BB 4
#define TT 2048
#define DD 128
#define HH 8
#define DK 16
#define KW 20          // smem K row stride (u32): 16 used (8 hi + 8 lo) + 4 pad
#define VW 68          // smem V^T d-row stride (u32): 64 used + 4 pad

__device__ float    g_Q[BB*TT*DD];
__device__ uint32_t g_Kw[BB*HH*TT*16];     // [bh][row][16]: w<8 hi pairs, w>=8 lo
__device__ uint32_t g_Vt[BB*HH*DK*(TT/2)]; // [bh][d][p]: pack(V[2p][d],V[2p+1][d])
__device__ float    g_ctx[BB*TT*DD];

__device__ __forceinline__ void mma_bf16(float c[4], const uint32_t a[4],
                                         uint32_t b0, uint32_t b1) {
    asm volatile(
        "mma.sync.aligned.m16n8k16.row.col.f32.bf16.bf16.f32 "
        "{%0,%1,%2,%3}, {%4,%5,%6,%7}, {%8,%9}, {%0,%1,%2,%3};"
        : "+f"(c[0]), "+f"(c[1]), "+f"(c[2]), "+f"(c[3])
        : "r"(a[0]), "r"(a[1]), "r"(a[2]), "r"(a[3]), "r"(b0), "r"(b1));
}
__device__ __forceinline__ uint32_t pack_bf16x2(float lo, float hi) {
    __nv_bfloat162 v = __floats2bfloat162_rn(lo, hi);
    return *reinterpret_cast<uint32_t*>(&v);
}
__device__ __forceinline__ void split_pair(float a, float b,
                                           uint32_t& hi, uint32_t& lo) {
    __nv_bfloat162 h2 = __floats2bfloat162_rn(a, b);
    __nv_bfloat162 l2 = __floats2bfloat162_rn(a - __bfloat162float(h2.x),
                                              b - __bfloat162float(h2.y));
    hi = *reinterpret_cast<uint32_t*>(&h2);
    lo = *reinterpret_cast<uint32_t*>(&l2);
}
__device__ __forceinline__ float ex2(float x) {
    float y; asm("ex2.approx.f32 %0, %1;" : "=f"(y) : "f"(x)); return y;
}
__device__ __forceinline__ void cpa16(uint32_t dst, const void* src) {
    asm volatile("cp.async.ca.shared.global [%0], [%1], 16;" :: "r"(dst), "l"(src));
}
__device__ __forceinline__ void cpa_wait() {
    asm volatile("cp.async.commit_group;\ncp.async.wait_group 0;" ::: "memory");
}

// ---------------------------------------------------------------------------
// Attention (round-10 best): grid (TT/64, BB*HH), 128 threads.
// Sweep 1: 1-term bf16 scores (normalizer); Sweep 2: 3-term scores.
// ---------------------------------------------------------------------------
__global__ void __launch_bounds__(128, 8)
attn_mma_kernel(const float* __restrict__ Qg,
                const uint32_t* __restrict__ Kw,
                const uint32_t* __restrict__ Vt,
                float* __restrict__ attn,
                float* __restrict__ ctx)
{
    __shared__ __align__(16) uint32_t sK[128 * KW];
    __shared__ __align__(16) uint32_t sV[DK * VW];

    const int tid  = threadIdx.x;
    const int lane = tid & 31;
    const int wq   = tid >> 5;
    const int g    = lane >> 2;
    const int t    = lane & 3;

    const int q0 = blockIdx.x * 64;
    const int bh = blockIdx.y;
    const int bb = bh >> 3;
    const int h  = bh & 7;
    const int r0 = q0 + wq * 16 + g;

    const uint32_t sKa = (uint32_t)__cvta_generic_to_shared(sK);
    const uint32_t sVa = (uint32_t)__cvta_generic_to_shared(sV);

    uint32_t ahi[4], alo[4];
    {
        const float sc = 0.360673760f;     // 0.25 * log2(e)
        const float* Qb = Qg + ((size_t)bb * TT + r0) * DD + h * DK;
        float2 x0 = *(const float2*)(Qb + 2 * t);
        float2 x1 = *(const float2*)(Qb + 8 * DD + 2 * t);
        float2 x2 = *(const float2*)(Qb + 2 * t + 8);
        float2 x3 = *(const float2*)(Qb + 8 * DD + 2 * t + 8);
        split_pair(sc * x0.x, sc * x0.y, ahi[0], alo[0]);
        split_pair(sc * x1.x, sc * x1.y, ahi[1], alo[1]);
        split_pair(sc * x2.x, sc * x2.y, ahi[2], alo[2]);
        split_pair(sc * x3.x, sc * x3.y, ahi[3], alo[3]);
    }

    // ---------------- sweep 1: rowsums (hi*hi only) ----------------
    float ps0 = 0.f, ps1 = 0.f;
    for (int kt = 0; kt < TT / 128; kt++) {
        __syncthreads();
        {
            const uint32_t* gk = Kw + ((size_t)bh * TT + kt * 128 + tid) * 16;
            const uint32_t dk0 = sKa + tid * (KW * 4);
            cpa16(dk0,      gk);
            cpa16(dk0 + 16, gk + 4);
        }
        cpa_wait();
        __syncthreads();
        #pragma unroll 4
        for (int ns = 0; ns < 16; ns++) {
            const int base = (ns * 8 + g) * KW + t;
            float C[4] = {0.f, 0.f, 0.f, 0.f};
            mma_bf16(C, ahi, sK[base], sK[base + 4]);
            ps0 += ex2(C[0]) + ex2(C[1]);
            ps1 += ex2(C[2]) + ex2(C[3]);
        }
    }
    ps0 += __shfl_xor_sync(0xffffffffu, ps0, 1);
    ps0 += __shfl_xor_sync(0xffffffffu, ps0, 2);
    ps1 += __shfl_xor_sync(0xffffffffu, ps1, 1);
    ps1 += __shfl_xor_sync(0xffffffffu, ps1, 2);
    const float lri0 = -__log2f(ps0);
    const float lri1 = -__log2f(ps1);

    // ---------------- sweep 2: 3-term scores, attn stores, PV ----------------
    float cc[2][4] = {{0.f,0.f,0.f,0.f},{0.f,0.f,0.f,0.f}};
    const size_t arow0 = ((size_t)bh * TT + r0) * TT;
    const size_t arow1 = arow0 + (size_t)8 * TT;

    for (int kt = 0; kt < TT / 128; kt++) {
        __syncthreads();
        {
            const uint32_t* gk = Kw + ((size_t)bh * TT + kt * 128 + tid) * 16;
            const uint32_t dk0 = sKa + tid * (KW * 4);
            #pragma unroll
            for (int c = 0; c < 4; c++) cpa16(dk0 + c * 16, gk + c * 4);
            #pragma unroll
            for (int c2 = 0; c2 < 2; c2++) {
                const int chunk = tid * 2 + c2;       // 0..255
                const int d  = chunk >> 4;
                const int cw = chunk & 15;
                cpa16(sVa + (d * VW + cw * 4) * 4,
                      Vt + ((size_t)bh * DK + d) * (TT / 2) + kt * 64 + cw * 4);
            }
        }
        cpa_wait();
        __syncthreads();

        #pragma unroll 2
        for (int j = 0; j < 8; j++) {
            uint32_t apk[4];
            #pragma unroll
            for (int nsl = 0; nsl < 2; nsl++) {
                const int base = ((j * 2 + nsl) * 8 + g) * KW + t;
                float C[4] = {lri0, lri0, lri1, lri1};
                mma_bf16(C, ahi, sK[base],     sK[base + 4]);
                mma_bf16(C, ahi, sK[base + 8], sK[base + 12]);
                mma_bf16(C, alo, sK[base],     sK[base + 4]);
                const float p0 = ex2(C[0]);
                const float p1 = ex2(C[1]);
                const float p2 = ex2(C[2]);
                const float p3 = ex2(C[3]);
                const int col = kt * 128 + j * 16 + nsl * 8 + 2 * t;
                *(float2*)(attn + arow0 + col) = make_float2(p0, p1);
                *(float2*)(attn + arow1 + col) = make_float2(p2, p3);
                apk[nsl ? 2 : 0] = pack_bf16x2(p0, p1);
                apk[nsl ? 3 : 1] = pack_bf16x2(p2, p3);
            }
            #pragma unroll
            for (int n2 = 0; n2 < 2; n2++) {
                const int vi = (n2 * 8 + g) * VW + 8 * j + t;
                mma_bf16(cc[n2], apk, sV[vi], sV[vi + 4]);
            }
        }
    }

    #pragma unroll
    for (int n2 = 0; n2 < 2; n2++) {
        float* cp = ctx + ((size_t)bb * TT + r0) * DD + h * DK + n2 * 8 + 2 * t;
        *(float2*)cp            = make_float2(cc[n2][0], cc[n2][1]);
        *(float2*)(cp + 8 * DD) = make_float2(cc[n2][2], cc[n2][3]);
    }
}

// ---------------------------------------------------------------------------
// Merged QKV projection: grid (rows/32, 3), 128 threads, 32 rows per block.
// y==0 -> Q fp32; y==1 -> K packed bf16 hi/lo; y==2 -> V^T packed bf16x2
// ---------------------------------------------------------------------------
__global__ void __launch_bounds__(128, 4)
proj3_kernel(const float* __restrict__ q,
             const float* __restrict__ k,
             const float* __restrict__ v,
             const float* __restrict__ Wq, const float* __restrict__ bq,
             const float* __restrict__ Wk, const float* __restrict__ bk,
             const float* __restrict__ Wv, const float* __restrict__ bv,
             float* __restrict__ Qd,
             uint32_t* __restrict__ Kw,
             uint32_t* __restrict__ Vt)
{
    const float* X; const float* W; const float* bias;
    if (blockIdx.y == 0)      { X = q; W = Wq; bias = bq; }
    else if (blockIdx.y == 1) { X = k; W = Wk; bias = bk; }
    else                      { X = v; W = Wv; bias = bv; }

    __shared__ float xs[32][132];
    const int tid  = threadIdx.x;
    const int row0 = blockIdx.x * 32;

    #pragma unroll
    for (int r = 0; r < 32; r++)
        xs[r][tid] = X[(size_t)(row0 + r) * DD + tid];
    __syncthreads();

    float acc[32];
    const float bvv = bias[tid];
    #pragma unroll
    for (int r = 0; r < 32; r++) acc[r] = bvv;

    #pragma unroll 2
    for (int kk = 0; kk < DD; kk += 4) {
        const float w0 = W[(kk + 0) * DD + tid];
        const float w1 = W[(kk + 1) * DD + tid];
        const float w2 = W[(kk + 2) * DD + tid];
        const float w3 = W[(kk + 3) * DD + tid];
        #pragma unroll
        for (int r = 0; r < 32; r++) {
            const float4 xv = *(const float4*)&xs[r][kk];
            acc[r] = fmaf(xv.x, w0, fmaf(xv.y, w1, fmaf(xv.z, w2, fmaf(xv.w, w3, acc[r]))));
        }
    }

    if (blockIdx.y == 0) {
        #pragma unroll
        for (int r = 0; r < 32; r++)
            Qd[(size_t)(row0 + r) * DD + tid] = acc[r];
        return;
    }

    __syncthreads();
    #pragma unroll
    for (int r = 0; r < 32; r++) xs[r][tid] = acc[r];
    __syncthreads();

    const int bbat = row0 >> 11;
    const int trow = row0 & 2047;

    if (blockIdx.y == 1) {
        // K: per row, per head: 8 hi words then 8 lo words (32 rows = 4096 words)
        #pragma unroll
        for (int i = 0; i < 32; i++) {
            const int widx = i * 128 + tid;
            const int r    = widx >> 7;          // 0..31
            const int rem  = widx & 127;
            const int hh2  = rem >> 4;
            const int w    = rem & 15;
            const int c    = hh2 * DK + (w & 7) * 2;
            const float a = xs[r][c], b = xs[r][c + 1];
            __nv_bfloat162 h2 = __floats2bfloat162_rn(a, b);
            uint32_t word;
            if (w < 8) word = *reinterpret_cast<uint32_t*>(&h2);
            else {
                __nv_bfloat162 l2 = __floats2bfloat162_rn(a - __bfloat162float(h2.x),
                                                          b - __bfloat162float(h2.y));
                word = *reinterpret_cast<uint32_t*>(&l2);
            }
            Kw[((size_t)(bbat * HH + hh2) * TT + trow + r) * 16 + w] = word;
        }
    } else {
        // V^T: word = pack(V[2p][d], V[2p+1][d]); 32 rows = 16 pairs x 128 hd
        const int p0 = trow >> 1;
        #pragma unroll
        for (int i = 0; i < 16; i++) {
            const int widx = i * 128 + tid;      // 0..2047
            const int hd  = widx >> 4;           // 0..127
            const int pl  = widx & 15;           // 0..15
            const int hh2 = hd >> 4, d = hd & 15;
            const int c   = hh2 * DK + d;
            const uint32_t word = pack_bf16x2(xs[2 * pl][c], xs[2 * pl + 1][c]);
            Vt[((size_t)(bbat * HH + hh2) * DK + d) * (TT / 2) + p0 + pl] = word;
        }
    }
}

// ---------------------------------------------------------------------------
// Output projection + residual + LayerNorm
// ---------------------------------------------------------------------------
__global__ void out_kernel(const float* __restrict__ ctxg,
                           const float* __restrict__ Wo,
                           const float* __restrict__ bo,
                           const float* __restrict__ resid,
                           const float* __restrict__ gamma,
                           const float* __restrict__ beta,
                           float* __restrict__ out)
{
    __shared__ float xs[16][132];
    __shared__ float mrow[16], rrow[16];
    const int tid  = threadIdx.x;
    const int row0 = blockIdx.x * 16;

    #pragma unroll
    for (int r = 0; r < 16; r++)
        xs[r][tid] = ctxg[(size_t)(row0 + r) * DD + tid];
    __syncthreads();

    float acc[16];
    const float bv = bo[tid];
    #pragma unroll
    for (int r = 0; r < 16; r++) acc[r] = bv;

    #pragma unroll 4
    for (int kk = 0; kk < DD; kk += 4) {
        const float w0 = Wo[(kk + 0) * DD + tid];
        const float w1 = Wo[(kk + 1) * DD + tid];
        const float w2 = Wo[(kk + 2) * DD + tid];
        const float w3 = Wo[(kk + 3) * DD + tid];
        #pragma unroll
        for (int r = 0; r < 16; r++) {
            const float4 xv = *(const float4*)&xs[r][kk];
            acc[r] = fmaf(xv.x, w0, fmaf(xv.y, w1, fmaf(xv.z, w2, fmaf(xv.w, w3, acc[r]))));
        }
    }
    __syncthreads();

    #pragma unroll
    for (int r = 0; r < 16; r++) {
        acc[r] += resid[(size_t)(row0 + r) * DD + tid];
        xs[r][tid] = acc[r];
    }
    __syncthreads();

    {
        const int r = tid >> 3, l8 = tid & 7;
        float s = 0.f, s2 = 0.f;
        for (int c = l8; c < 128; c += 8) {
            const float v = xs[r][c];
            s += v; s2 = fmaf(v, v, s2);
        }
        #pragma unroll
        for (int off = 4; off > 0; off >>= 1) {
            s  += __shfl_down_sync(0xffffffffu, s,  off, 8);
            s2 += __shfl_down_sync(0xffffffffu, s2, off, 8);
        }
        if (l8 == 0) {
            const float m   = s * (1.f / 128.f);
            const float var = s2 * (1.f / 128.f) - m * m;
            mrow[r] = m;
            rrow[r] = rsqrtf(var + 1e-5f);
        }
    }
    __syncthreads();

    const float gm = gamma[tid], bt = beta[tid];
    #pragma unroll
    for (int r = 0; r < 16; r++)
        out[(size_t)(row0 + r) * DD + tid] = (acc[r] - mrow[r]) * rrow[r] * gm + bt;
}

// ---------------------------------------------------------------------------
extern "C" void kernel_launch(void* const* d_in, const int* in_sizes, int n_in,
                              void* d_out, int out_size)
{
    const float* queries = (const float*)d_in[0];
    const float* keys    = (const float*)d_in[1];
    const float* values  = (const float*)d_in[2];
    const float* Wq      = (const float*)d_in[3];
    const float* bq      = (const float*)d_in[4];
    const float* Wk      = (const float*)d_in[5];
    const float* bk      = (const float*)d_in[6];
    const float* Wv      = (const float*)d_in[7];
    const float* bv      = (const float*)d_in[8];
    const float* Wo      = (const float*)d_in[9];
    const float* bo      = (const float*)d_in[10];
    const float* gamma   = (const float*)d_in[11];
    const float* beta    = (const float*)d_in[12];

    float* out  = (float*)d_out;
    float* attn = out + (size_t)BB * TT * DD;

    float *Qd, *Cd; uint32_t *Kwp, *Vtp;
    cudaGetSymbolAddress((void**)&Qd,  g_Q);
    cudaGetSymbolAddress((void**)&Kwp, g_Kw);
    cudaGetSymbolAddress((void**)&Vtp, g_Vt);
    cudaGetSymbolAddress((void**)&Cd,  g_ctx);

    const int rows = BB * TT;
    proj3_kernel<<<dim3(rows / 32, 3), 128>>>(queries, keys, values,
                                              Wq, bq, Wk, bk, Wv, bv,
                                              Qd, Kwp, Vtp);

    attn_mma_kernel<<<dim3(TT / 64, BB * HH), 128>>>(Qd, Kwp, Vtp, attn, Cd);

    out_kernel<<<rows / 16, 128>>>(Cd, Wo, bo, queries, gamma, beta, out);
}

// round 14
// speedup vs baseline: 1.7432x; 1.6987x over previous
#include <cuda_runtime.h>
#include <cuda_fp16.h>
#include <stdint.h>
#include <math.h>

#define BB 4
#define TT 2048
#define DD 128
#define HH 8
#define DK 16
#define KW 12          // smem K row stride (u32): 8 used + 4 pad
#define VW 68          // smem V^T d-row stride (u32): 64 used + 4 pad

__device__ float    g_Q[BB*TT*DD];
__device__ uint32_t g_Kw[BB*HH*TT*8];      // [bh][row][8]: f16 pairs (cols 2w,2w+1)
__device__ uint32_t g_Vt[BB*HH*DK*(TT/2)]; // [bh][d][p]: f16 pack(V[2p][d],V[2p+1][d])
__device__ float    g_ctx[BB*TT*DD];

__device__ __forceinline__ void mma_f16(float c[4], const uint32_t a[4],
                                        uint32_t b0, uint32_t b1) {
    asm volatile(
        "mma.sync.aligned.m16n8k16.row.col.f32.f16.f16.f32 "
        "{%0,%1,%2,%3}, {%4,%5,%6,%7}, {%8,%9}, {%0,%1,%2,%3};"
        : "+f"(c[0]), "+f"(c[1]), "+f"(c[2]), "+f"(c[3])
        : "r"(a[0]), "r"(a[1]), "r"(a[2]), "r"(a[3]), "r"(b0), "r"(b1));
}
__device__ __forceinline__ uint32_t pack_h2(float lo, float hi) {
    __half2 v = __floats2half2_rn(lo, hi);     // .x = lo half
    return *reinterpret_cast<uint32_t*>(&v);
}
__device__ __forceinline__ float ex2(float x) {
    float y; asm("ex2.approx.f32 %0, %1;" : "=f"(y) : "f"(x)); return y;
}
__device__ __forceinline__ void cpa16(uint32_t dst, const void* src) {
    asm volatile("cp.async.ca.shared.global [%0], [%1], 16;" :: "r"(dst), "l"(src));
}
__device__ __forceinline__ void cpa_wait() {
    asm volatile("cp.async.commit_group;\ncp.async.wait_group 0;" ::: "memory");
}

// ---------------------------------------------------------------------------
// Attention: grid (TT/64, BB*HH), 128 threads = 4 warps x one m16 fragment.
// Scores: single f16 MMA, identical in both sweeps (rows sum exactly to 1).
// ---------------------------------------------------------------------------
__global__ void __launch_bounds__(128, 8)
attn_mma_kernel(const float* __restrict__ Qg,
                const uint32_t* __restrict__ Kw,
                const uint32_t* __restrict__ Vt,
                float* __restrict__ attn,
                float* __restrict__ ctx)
{
    __shared__ __align__(16) uint32_t sK[128 * KW];
    __shared__ __align__(16) uint32_t sV[DK * VW];

    const int tid  = threadIdx.x;
    const int lane = tid & 31;
    const int wq   = tid >> 5;
    const int g    = lane >> 2;
    const int t    = lane & 3;

    const int q0 = blockIdx.x * 64;
    const int bh = blockIdx.y;
    const int bb = bh >> 3;
    const int h  = bh & 7;
    const int r0 = q0 + wq * 16 + g;

    const uint32_t sKa = (uint32_t)__cvta_generic_to_shared(sK);
    const uint32_t sVa = (uint32_t)__cvta_generic_to_shared(sV);
    const uint32_t* gkb = Kw + ((size_t)bh * TT + tid) * 8;

    // Q fragment: f16, prescaled by 0.25*log2(e)
    uint32_t ahi[4];
    {
        const float sc = 0.360673760f;     // 0.25 * log2(e)
        const float* Qb = Qg + ((size_t)bb * TT + r0) * DD + h * DK;
        float2 x0 = *(const float2*)(Qb + 2 * t);
        float2 x1 = *(const float2*)(Qb + 8 * DD + 2 * t);
        float2 x2 = *(const float2*)(Qb + 2 * t + 8);
        float2 x3 = *(const float2*)(Qb + 8 * DD + 2 * t + 8);
        ahi[0] = pack_h2(sc * x0.x, sc * x0.y);
        ahi[1] = pack_h2(sc * x1.x, sc * x1.y);
        ahi[2] = pack_h2(sc * x2.x, sc * x2.y);
        ahi[3] = pack_h2(sc * x3.x, sc * x3.y);
    }

    // ---------------- sweep 1: rowsums ----------------
    float ps0 = 0.f, ps1 = 0.f;
    for (int kt = 0; kt < TT / 128; kt++) {
        __syncthreads();
        {
            const uint32_t* gk = gkb + (size_t)kt * 128 * 8;
            const uint32_t dk0 = sKa + tid * (KW * 4);
            cpa16(dk0,      gk);
            cpa16(dk0 + 16, gk + 4);
        }
        cpa_wait();
        __syncthreads();
        #pragma unroll 4
        for (int ns = 0; ns < 16; ns++) {
            const int base = (ns * 8 + g) * KW + t;
            float C[4] = {0.f, 0.f, 0.f, 0.f};
            mma_f16(C, ahi, sK[base], sK[base + 4]);
            ps0 += ex2(C[0]) + ex2(C[1]);
            ps1 += ex2(C[2]) + ex2(C[3]);
        }
    }
    ps0 += __shfl_xor_sync(0xffffffffu, ps0, 1);
    ps0 += __shfl_xor_sync(0xffffffffu, ps0, 2);
    ps1 += __shfl_xor_sync(0xffffffffu, ps1, 1);
    ps1 += __shfl_xor_sync(0xffffffffu, ps1, 2);
    const float lri0 = -__log2f(ps0);
    const float lri1 = -__log2f(ps1);

    // ---------------- sweep 2: scores, attn stores, PV ----------------
    float cc[2][4] = {{0.f,0.f,0.f,0.f},{0.f,0.f,0.f,0.f}};
    const size_t arow0 = ((size_t)bh * TT + r0) * TT;
    const size_t arow1 = arow0 + (size_t)8 * TT;

    for (int kt = 0; kt < TT / 128; kt++) {
        __syncthreads();
        {
            const uint32_t* gk = gkb + (size_t)kt * 128 * 8;
            const uint32_t dk0 = sKa + tid * (KW * 4);
            cpa16(dk0,      gk);
            cpa16(dk0 + 16, gk + 4);
            #pragma unroll
            for (int c2 = 0; c2 < 2; c2++) {
                const int chunk = tid * 2 + c2;       // 0..255
                const int d  = chunk >> 4;
                const int cw = chunk & 15;
                cpa16(sVa + (d * VW + cw * 4) * 4,
                      Vt + ((size_t)bh * DK + d) * (TT / 2) + kt * 64 + cw * 4);
            }
        }
        cpa_wait();
        __syncthreads();

        #pragma unroll 2
        for (int j = 0; j < 8; j++) {
            uint32_t apk[4];
            #pragma unroll
            for (int nsl = 0; nsl < 2; nsl++) {
                const int base = ((j * 2 + nsl) * 8 + g) * KW + t;
                float C[4] = {lri0, lri0, lri1, lri1};
                mma_f16(C, ahi, sK[base], sK[base + 4]);
                const float p0 = ex2(C[0]);
                const float p1 = ex2(C[1]);
                const float p2 = ex2(C[2]);
                const float p3 = ex2(C[3]);
                const int col = kt * 128 + j * 16 + nsl * 8 + 2 * t;
                *(float2*)(attn + arow0 + col) = make_float2(p0, p1);
                *(float2*)(attn + arow1 + col) = make_float2(p2, p3);
                apk[nsl ? 2 : 0] = pack_h2(p0, p1);
                apk[nsl ? 3 : 1] = pack_h2(p2, p3);
            }
            #pragma unroll
            for (int n2 = 0; n2 < 2; n2++) {
                const int vi = (n2 * 8 + g) * VW + 8 * j + t;
                mma_f16(cc[n2], apk, sV[vi], sV[vi + 4]);
            }
        }
    }

    #pragma unroll
    for (int n2 = 0; n2 < 2; n2++) {
        float* cp = ctx + ((size_t)bb * TT + r0) * DD + h * DK + n2 * 8 + 2 * t;
        *(float2*)cp            = make_float2(cc[n2][0], cc[n2][1]);
        *(float2*)(cp + 8 * DD) = make_float2(cc[n2][2], cc[n2][3]);
    }
}

// ---------------------------------------------------------------------------
// Merged QKV projection: grid (rows/32, 3), 128 threads, 32 rows per block.
// y==0 -> Q fp32; y==1 -> K f16 pairs; y==2 -> V^T f16 pairs
// ---------------------------------------------------------------------------
__global__ void __launch_bounds__(128, 4)
proj3_kernel(const float* __restrict__ q,
             const float* __restrict__ k,
             const float* __restrict__ v,
             const float* __restrict__ Wq, const float* __restrict__ bq,
             const float* __restrict__ Wk, const float* __restrict__ bk,
             const float* __restrict__ Wv, const float* __restrict__ bv,
             float* __restrict__ Qd,
             uint32_t* __restrict__ Kw,
             uint32_t* __restrict__ Vt)
{
    const float* X; const float* W; const float* bias;
    if (blockIdx.y == 0)      { X = q; W = Wq; bias = bq; }
    else if (blockIdx.y == 1) { X = k; W = Wk; bias = bk; }
    else                      { X = v; W = Wv; bias = bv; }

    __shared__ float xs[32][132];
    const int tid  = threadIdx.x;
    const int row0 = blockIdx.x * 32;

    #pragma unroll
    for (int r = 0; r < 32; r++)
        xs[r][tid] = X[(size_t)(row0 + r) * DD + tid];
    __syncthreads();

    float acc[32];
    const float bvv = bias[tid];
    #pragma unroll
    for (int r = 0; r < 32; r++) acc[r] = bvv;

    #pragma unroll 2
    for (int kk = 0; kk < DD; kk += 4) {
        const float w0 = W[(kk + 0) * DD + tid];
        const float w1 = W[(kk + 1) * DD + tid];
        const float w2 = W[(kk + 2) * DD + tid];
        const float w3 = W[(kk + 3) * DD + tid];
        #pragma unroll
        for (int r = 0; r < 32; r++) {
            const float4 xv = *(const float4*)&xs[r][kk];
            acc[r] = fmaf(xv.x, w0, fmaf(xv.y, w1, fmaf(xv.z, w2, fmaf(xv.w, w3, acc[r]))));
        }
    }

    if (blockIdx.y == 0) {
        #pragma unroll
        for (int r = 0; r < 32; r++)
            Qd[(size_t)(row0 + r) * DD + tid] = acc[r];
        return;
    }

    __syncthreads();
    #pragma unroll
    for (int r = 0; r < 32; r++) xs[r][tid] = acc[r];
    __syncthreads();

    const int bbat = row0 >> 11;
    const int trow = row0 & 2047;

    if (blockIdx.y == 1) {
        // K: 32 rows x 8 heads x 8 f16-pair words = 2048 words
        #pragma unroll
        for (int i = 0; i < 16; i++) {
            const int widx = i * 128 + tid;      // 0..2047
            const int r    = widx >> 6;          // 0..31
            const int rem  = widx & 63;
            const int hh2  = rem >> 3;           // head
            const int w    = rem & 7;
            const int c    = hh2 * DK + w * 2;
            const uint32_t word = pack_h2(xs[r][c], xs[r][c + 1]);
            Kw[((size_t)(bbat * HH + hh2) * TT + trow + r) * 8 + w] = word;
        }
    } else {
        // V^T: word = pack(V[2p][d], V[2p+1][d]); 32 rows = 16 pairs x 128 hd
        const int p0 = trow >> 1;
        #pragma unroll
        for (int i = 0; i < 16; i++) {
            const int widx = i * 128 + tid;      // 0..2047
            const int hd  = widx >> 4;           // 0..127
            const int pl  = widx & 15;           // 0..15
            const int hh2 = hd >> 4, d = hd & 15;
            const int c   = hh2 * DK + d;
            const uint32_t word = pack_h2(xs[2 * pl][c], xs[2 * pl + 1][c]);
            Vt[((size_t)(bbat * HH + hh2) * DK + d) * (TT / 2) + p0 + pl] = word;
        }
    }
}

// ---------------------------------------------------------------------------
// Output projection + residual + LayerNorm
// ---------------------------------------------------------------------------
__global__ void out_kernel(const float* __restrict__ ctxg,
                           const float* __restrict__ Wo,
                           const float* __restrict__ bo,
                           const float* __restrict__ resid,
                           const float* __restrict__ gamma,
                           const float* __restrict__ beta,
                           float* __restrict__ out)
{
    __shared__ float xs[16][132];
    __shared__ float mrow[16], rrow[16];
    const int tid  = threadIdx.x;
    const int row0 = blockIdx.x * 16;

    #pragma unroll
    for (int r = 0; r < 16; r++)
        xs[r][tid] = ctxg[(size_t)(row0 + r) * DD + tid];
    __syncthreads();

    float acc[16];
    const float bv = bo[tid];
    #pragma unroll
    for (int r = 0; r < 16; r++) acc[r] = bv;

    #pragma unroll 4
    for (int kk = 0; kk < DD; kk += 4) {
        const float w0 = Wo[(kk + 0) * DD + tid];
        const float w1 = Wo[(kk + 1) * DD + tid];
        const float w2 = Wo[(kk + 2) * DD + tid];
        const float w3 = Wo[(kk + 3) * DD + tid];
        #pragma unroll
        for (int r = 0; r < 16; r++) {
            const float4 xv = *(const float4*)&xs[r][kk];
            acc[r] = fmaf(xv.x, w0, fmaf(xv.y, w1, fmaf(xv.z, w2, fmaf(xv.w, w3, acc[r]))));
        }
    }
    __syncthreads();

    #pragma unroll
    for (int r = 0; r < 16; r++) {
        acc[r] += resid[(size_t)(row0 + r) * DD + tid];
        xs[r][tid] = acc[r];
    }
    __syncthreads();

    {
        const int r = tid >> 3, l8 = tid & 7;
        float s = 0.f, s2 = 0.f;
        for (int c = l8; c < 128; c += 8) {
            const float v = xs[r][c];
            s += v; s2 = fmaf(v, v, s2);
        }
        #pragma unroll
        for (int off = 4; off > 0; off >>= 1) {
            s  += __shfl_down_sync(0xffffffffu, s,  off, 8);
            s2 += __shfl_down_sync(0xffffffffu, s2, off, 8);
        }
        if (l8 == 0) {
            const float m   = s * (1.f / 128.f);
            const float var = s2 * (1.f / 128.f) - m * m;
            mrow[r] = m;
            rrow[r] = rsqrtf(var + 1e-5f);
        }
    }
    __syncthreads();

    const float gm = gamma[tid], bt = beta[tid];
    #pragma unroll
    for (int r = 0; r < 16; r++)
        out[(size_t)(row0 + r) * DD + tid] = (acc[r] - mrow[r]) * rrow[r] * gm + bt;
}

// ---------------------------------------------------------------------------
extern "C" void kernel_launch(void* const* d_in, const int* in_sizes, int n_in,
                              void* d_out, int out_size)
{
    const float* queries = (const float*)d_in[0];
    const float* keys    = (const float*)d_in[1];
    const float* values  = (const float*)d_in[2];
    const float* Wq      = (const float*)d_in[3];
    const float* bq      = (const float*)d_in[4];
    const float* Wk      = (const float*)d_in[5];
    const float* bk      = (const float*)d_in[6];
    const float* Wv      = (const float*)d_in[7];
    const float* bv      = (const float*)d_in[8];
    const float* Wo      = (const float*)d_in[9];
    const float* bo      = (const float*)d_in[10];
    const float* gamma   = (const float*)d_in[11];
    const float* beta    = (const float*)d_in[12];

    float* out  = (float*)d_out;
    float* attn = out + (size_t)BB * TT * DD;

    float *Qd, *Cd; uint32_t *Kwp, *Vtp;
    cudaGetSymbolAddress((void**)&Qd,  g_Q);
    cudaGetSymbolAddress((void**)&Kwp, g_Kw);
    cudaGetSymbolAddress((void**)&Vtp, g_Vt);
    cudaGetSymbolAddress((void**)&Cd,  g_ctx);

    const int rows = BB * TT;
    proj3_kernel<<<dim3(rows / 32, 3), 128>>>(queries, keys, values,
                                              Wq, bq, Wk, bk, Wv, bv,
                                              Qd, Kwp, Vtp);

    attn_mma_kernel<<<dim3(TT / 64, BB * HH), 128>>>(Qd, Kwp, Vtp, attn, Cd);

    out_kernel<<<rows / 16, 128>>>(Cd, Wo, bo, queries, gamma, beta, out);
}